// round 2
// baseline (speedup 1.0000x reference)
#include <cuda_runtime.h>

// Cosine-similarity discriminator (persistent grid-stride version):
//   out[b, n]     = cos(s_row, h_rl_row)   (torch F.normalize semantics, eps=1e-12)
//   out[b, N + n] = cos(s_row, h_fk_row)
// Shapes: s, h_rl, h_fk : [B=8, N=8192, D=512] fp32 ; out : [B, 2N] fp32.
//
// One warp per row, persistent launch (~1 resident wave), each warp streams
// ~7 rows back-to-back so the DRAM load queue never drains across wave
// boundaries. Per row: 12 coalesced LDG.128 per lane-group, 5 dot-product
// accumulators, butterfly shuffle reduce, lane 0 writes 2 floats.

#define D 512
#define NROW_N 8192
#define WARPS_PER_BLOCK 8
#define THREADS (WARPS_PER_BLOCK * 32)
// ~8 CTAs/SM on 148-152 SMs -> one resident wave, slight overshoot is fine.
#define GRID_BLOCKS 1216

__global__ __launch_bounds__(THREADS)
void cosine_pair_persistent(const float* __restrict__ s,
                            const float* __restrict__ h_rl,
                            const float* __restrict__ h_fk,
                            float* __restrict__ out,
                            int total_rows)
{
    const int lane       = threadIdx.x & 31;
    const int warp_id    = blockIdx.x * WARPS_PER_BLOCK + (threadIdx.x >> 5);
    const int num_warps  = gridDim.x * WARPS_PER_BLOCK;

    for (int row = warp_id; row < total_rows; row += num_warps) {
        const size_t base = (size_t)row * D;
        const float4* __restrict__ s4 = reinterpret_cast<const float4*>(s    + base);
        const float4* __restrict__ a4 = reinterpret_cast<const float4*>(h_rl + base);
        const float4* __restrict__ b4 = reinterpret_cast<const float4*>(h_fk + base);

        float ss = 0.f, aa = 0.f, bb = 0.f, sa = 0.f, sb = 0.f;

        // 128 float4 per row / 32 lanes = 4 iterations of 3 loads each.
        // Front-batch the loads for memory-level parallelism.
        float4 vs[4], va[4], vb[4];
#pragma unroll
        for (int i = 0; i < 4; ++i) {
            vs[i] = s4[i * 32 + lane];
            va[i] = a4[i * 32 + lane];
            vb[i] = b4[i * 32 + lane];
        }
#pragma unroll
        for (int i = 0; i < 4; ++i) {
            const float4 x = vs[i], y = va[i], z = vb[i];
            ss += x.x * x.x + x.y * x.y + x.z * x.z + x.w * x.w;
            aa += y.x * y.x + y.y * y.y + y.z * y.z + y.w * y.w;
            bb += z.x * z.x + z.y * z.y + z.z * z.z + z.w * z.w;
            sa += x.x * y.x + x.y * y.y + x.z * y.z + x.w * y.w;
            sb += x.x * z.x + x.y * z.y + x.z * z.z + x.w * z.w;
        }

        // Butterfly reduction over 5 values.
#pragma unroll
        for (int off = 16; off > 0; off >>= 1) {
            ss += __shfl_xor_sync(0xffffffffu, ss, off);
            aa += __shfl_xor_sync(0xffffffffu, aa, off);
            bb += __shfl_xor_sync(0xffffffffu, bb, off);
            sa += __shfl_xor_sync(0xffffffffu, sa, off);
            sb += __shfl_xor_sync(0xffffffffu, sb, off);
        }

        if (lane == 0) {
            const float eps = 1e-12f;
            const float ns = fmaxf(sqrtf(ss), eps);
            const float na = fmaxf(sqrtf(aa), eps);
            const float nb = fmaxf(sqrtf(bb), eps);

            const int b = row >> 13;             // row / 8192
            const int n = row & (NROW_N - 1);    // row % 8192
            float* obase = out + (size_t)b * (2 * NROW_N);
            obase[n]          = sa / (ns * na);
            obase[NROW_N + n] = sb / (ns * nb);
        }
    }
}

extern "C" void kernel_launch(void* const* d_in, const int* in_sizes, int n_in,
                              void* d_out, int out_size)
{
    const float* s    = (const float*)d_in[0];
    const float* h_rl = (const float*)d_in[1];
    const float* h_fk = (const float*)d_in[2];
    float* out = (float*)d_out;

    const int total_rows = in_sizes[0] / D;   // B*N = 65536

    cosine_pair_persistent<<<GRID_BLOCKS, THREADS>>>(s, h_rl, h_fk, out, total_rows);
}

// round 3
// speedup vs baseline: 1.1328x; 1.1328x over previous
#include <cuda_runtime.h>

// Cosine-similarity discriminator:
//   out[b, n]     = cos(s_row, h_rl_row)   (torch F.normalize, eps=1e-12)
//   out[b, N + n] = cos(s_row, h_fk_row)
// Shapes: s, h_rl, h_fk : [B=8, N=8192, D=512] fp32 ; out : [B, 2N] fp32.
//
// One warp per row, fully oversubscribed launch (8192 CTAs) — the HW scheduler
// overlaps retiring warps' reduction tails with fresh warps' loads.
// __launch_bounds__(256, 8) forces <=32 regs -> 64 warps/SM (full occupancy).
// Loads are double-buffered in groups of 6 float4 (24 regs live) so the
// allocator fits 32 regs without spilling.

#define D 512
#define NROW_N 8192
#define WARPS_PER_BLOCK 8
#define THREADS (WARPS_PER_BLOCK * 32)

__global__ __launch_bounds__(THREADS, 8)
void cosine_pair_kernel(const float* __restrict__ s,
                        const float* __restrict__ h_rl,
                        const float* __restrict__ h_fk,
                        float* __restrict__ out,
                        int total_rows)
{
    const int warp_id = blockIdx.x * WARPS_PER_BLOCK + (threadIdx.x >> 5);
    const int lane    = threadIdx.x & 31;
    if (warp_id >= total_rows) return;

    const size_t base = (size_t)warp_id * D;
    const float4* __restrict__ s4 = reinterpret_cast<const float4*>(s    + base);
    const float4* __restrict__ a4 = reinterpret_cast<const float4*>(h_rl + base);
    const float4* __restrict__ b4 = reinterpret_cast<const float4*>(h_fk + base);

    float ss = 0.f, aa = 0.f, bb = 0.f, sa = 0.f, sb = 0.f;

    // 128 float4 per row / 32 lanes = 4 logical iterations; process them as
    // 2 half-batches of 6 loads (2 iters x 3 tensors) each.
#pragma unroll
    for (int h = 0; h < 2; ++h) {
        float4 vs0 = s4[(2 * h + 0) * 32 + lane];
        float4 va0 = a4[(2 * h + 0) * 32 + lane];
        float4 vb0 = b4[(2 * h + 0) * 32 + lane];
        float4 vs1 = s4[(2 * h + 1) * 32 + lane];
        float4 va1 = a4[(2 * h + 1) * 32 + lane];
        float4 vb1 = b4[(2 * h + 1) * 32 + lane];

        ss += vs0.x * vs0.x + vs0.y * vs0.y + vs0.z * vs0.z + vs0.w * vs0.w;
        aa += va0.x * va0.x + va0.y * va0.y + va0.z * va0.z + va0.w * va0.w;
        bb += vb0.x * vb0.x + vb0.y * vb0.y + vb0.z * vb0.z + vb0.w * vb0.w;
        sa += vs0.x * va0.x + vs0.y * va0.y + vs0.z * va0.z + vs0.w * va0.w;
        sb += vs0.x * vb0.x + vs0.y * vb0.y + vs0.z * vb0.z + vs0.w * vb0.w;

        ss += vs1.x * vs1.x + vs1.y * vs1.y + vs1.z * vs1.z + vs1.w * vs1.w;
        aa += va1.x * va1.x + va1.y * va1.y + va1.z * va1.z + va1.w * va1.w;
        bb += vb1.x * vb1.x + vb1.y * vb1.y + vb1.z * vb1.z + vb1.w * vb1.w;
        sa += vs1.x * va1.x + vs1.y * va1.y + vs1.z * va1.z + vs1.w * va1.w;
        sb += vs1.x * vb1.x + vs1.y * vb1.y + vs1.z * vb1.z + vs1.w * vb1.w;
    }

    // Butterfly reduction over the 5 partial sums.
#pragma unroll
    for (int off = 16; off > 0; off >>= 1) {
        ss += __shfl_xor_sync(0xffffffffu, ss, off);
        aa += __shfl_xor_sync(0xffffffffu, aa, off);
        bb += __shfl_xor_sync(0xffffffffu, bb, off);
        sa += __shfl_xor_sync(0xffffffffu, sa, off);
        sb += __shfl_xor_sync(0xffffffffu, sb, off);
    }

    if (lane == 0) {
        const float eps = 1e-12f;
        const float ns = fmaxf(sqrtf(ss), eps);
        const float na = fmaxf(sqrtf(aa), eps);
        const float nb = fmaxf(sqrtf(bb), eps);

        const int b = warp_id >> 13;             // / 8192
        const int n = warp_id & (NROW_N - 1);    // % 8192
        float* obase = out + (size_t)b * (2 * NROW_N);
        obase[n]          = sa / (ns * na);
        obase[NROW_N + n] = sb / (ns * nb);
    }
}

extern "C" void kernel_launch(void* const* d_in, const int* in_sizes, int n_in,
                              void* d_out, int out_size)
{
    const float* s    = (const float*)d_in[0];
    const float* h_rl = (const float*)d_in[1];
    const float* h_fk = (const float*)d_in[2];
    float* out = (float*)d_out;

    const int total_rows = in_sizes[0] / D;   // B*N = 65536
    const int blocks = (total_rows + WARPS_PER_BLOCK - 1) / WARPS_PER_BLOCK;

    cosine_pair_kernel<<<blocks, THREADS>>>(s, h_rl, h_fk, out, total_rows);
}